// round 6
// baseline (speedup 1.0000x reference)
#include <cuda_runtime.h>

#define NMAX 20000
#define EMAX 320000
#define FDIM 128
#define PHI_COLS 384
#define NRBF 20
#define NPB 4   // nodes per block in the gather kernel

typedef unsigned long long ull;

// ---------------- scratch (static __device__, no allocations) ----------------
__device__ __align__(16) float g_T[(size_t)NMAX * FDIM];        // silu(h@W1+b1)
__device__ __align__(16) float g_phi[(size_t)NMAX * PHI_COLS];  // phi
__device__ int   g_deg[NMAX];
__device__ int   g_off[NMAX];
__device__ int   g_cur[NMAX];
__device__ int   g_srcs[EMAX];              // sorted-by-dst: src node id
__device__ float g_sd[EMAX];                // sorted-by-dst: d_ij
__device__ float g_sfc[EMAX];               // sorted-by-dst: fcut
__device__ __align__(16) float g_su[(size_t)3 * EMAX];          // sorted-by-dst: unit_r
__device__ __align__(16) ulonglong2 g_rbf[(size_t)EMAX * 10];   // sorted: 20 dup'd t-pairs/edge
__device__ int   g_is64;   // 1 if nbrs is int64 pairs, 0 if int32 pairs

// ---------------- packed f32x2 helpers (sm_103a) ----------------
__device__ __forceinline__ ull pk2(float x, float y) {
    ull r; asm("mov.b64 %0, {%1, %2};" : "=l"(r) : "f"(x), "f"(y)); return r;
}
__device__ __forceinline__ float2 upk2(ull a) {
    float2 r; asm("mov.b64 {%0, %1}, %2;" : "=f"(r.x), "=f"(r.y) : "l"(a)); return r;
}
__device__ __forceinline__ ull ffma2(ull a, ull b, ull c) {
    ull d; asm("fma.rn.f32x2 %0, %1, %2, %3;" : "=l"(d) : "l"(a), "l"(b), "l"(c)); return d;
}
__device__ __forceinline__ ull fmul2(ull a, ull b) {
    ull d; asm("mul.rn.f32x2 %0, %1, %2;" : "=l"(d) : "l"(a), "l"(b)); return d;
}
__device__ __forceinline__ ull fadd2(ull a, ull b) {
    ull d; asm("add.rn.f32x2 %0, %1, %2;" : "=l"(d) : "l"(a), "l"(b)); return d;
}

__device__ __forceinline__ int2 edge_pair(const void* __restrict__ nbrs, size_t e, int is64) {
    if (is64) {
        const long long* p = (const long long*)nbrs;
        return make_int2((int)p[2 * e], (int)p[2 * e + 1]);
    } else {
        return ((const int2*)nbrs)[e];
    }
}

// ---------------- fused init: zero degrees + nbrs dtype detect ----------------
__global__ void init_kernel(const int* __restrict__ w, int nwords, int Nn) {
    int i = blockIdx.x * 256 + threadIdx.x;
    if (i < Nn) g_deg[i] = 0;
    if (i == 0) {
        int any = 0;
        int lim = nwords < 32 ? nwords : 32;
        for (int k = 1; k < lim; k += 2) any |= w[k];
        g_is64 = (any == 0) ? 1 : 0;
    }
}

__global__ void hist_kernel(const void* __restrict__ nbrs, int E) {
    int is64 = g_is64;
    int e = blockIdx.x * 256 + threadIdx.x;
    if (e < E) {
        int2 p = edge_pair(nbrs, (size_t)e, is64);
        atomicAdd(&g_deg[p.x], 1);
    }
}

// single block, 1024 threads, 20 elems/thread compile-time unrolled, chunked by 20480
__global__ void scan_kernel(int Nn) {
    __shared__ int warpsum[32];
    int t = threadIdx.x, lane = t & 31, w = t >> 5;
    int run = 0;
    for (int base = 0; base < Nn; base += 20480) {
        int vals[20];
        int s = 0;
        int i0 = base + t * 20;
#pragma unroll
        for (int k = 0; k < 20; ++k) {
            int i = i0 + k;
            int v = (i < Nn) ? g_deg[i] : 0;
            vals[k] = s;
            s += v;
        }
        int x = s;
#pragma unroll
        for (int off = 1; off < 32; off <<= 1) {
            int y = __shfl_up_sync(0xFFFFFFFFu, x, off);
            if (lane >= off) x += y;
        }
        if (lane == 31) warpsum[w] = x;
        __syncthreads();
        if (w == 0) {
            int y = warpsum[lane];
#pragma unroll
            for (int off = 1; off < 32; off <<= 1) {
                int z = __shfl_up_sync(0xFFFFFFFFu, y, off);
                if (lane >= off) y += z;
            }
            warpsum[lane] = y;
        }
        __syncthreads();
        int excl = run + x - s + ((w > 0) ? warpsum[w - 1] : 0);
#pragma unroll
        for (int k = 0; k < 20; ++k) {
            int i = i0 + k;
            if (i < Nn) { g_off[i] = excl + vals[k]; g_cur[i] = excl + vals[k]; }
        }
        run += warpsum[31];
        __syncthreads();
    }
}

// scatter edges into dst-sorted arrays (src, d, unit_r)
__global__ void scatter_kernel(const void* __restrict__ nbrs,
                               const float* __restrict__ d_ij,
                               const float* __restrict__ ur, int E) {
    int is64 = g_is64;
    int e = blockIdx.x * 256 + threadIdx.x;
    if (e < E) {
        int2 p = edge_pair(nbrs, (size_t)e, is64);
        int pos = atomicAdd(&g_cur[p.x], 1);
        g_srcs[pos] = p.y;
        g_sd[pos] = d_ij[e];
        g_su[3 * (size_t)pos + 0] = ur[3 * (size_t)e + 0];
        g_su[3 * (size_t)pos + 1] = ur[3 * (size_t)e + 1];
        g_su[3 * (size_t)pos + 2] = ur[3 * (size_t)e + 2];
    }
}

// per-edge RBF precompute: t_n = sin(n*pi*d/5) * fcut / d, stored as duplicated f32 pairs
__global__ void rbf_kernel(int E) {
    int e = blockIdx.x * 256 + threadIdx.x;
    if (e >= E) return;
    float d = g_sd[e];
    float x = d * 0.62831853071795864769f;  // pi/5
    float s, c;
    __sincosf(x, &s, &c);
    float fc = (d < 5.0f) ? 0.5f * (c + 1.0f) : 0.0f;
    float scale = __frcp_rn(d) * fc;
    float twoc = c + c;
    float sp = 0.0f, sn = s;
    ulonglong2 buf[10];
#pragma unroll
    for (int r2 = 0; r2 < 10; ++r2) {
        float t0 = sn * scale;
        float s2 = __fmaf_rn(twoc, sn, -sp); sp = sn; sn = s2;
        float t1 = sn * scale;
        s2 = __fmaf_rn(twoc, sn, -sp); sp = sn; sn = s2;
        buf[r2].x = pk2(t0, t0);
        buf[r2].y = pk2(t1, t1);
    }
    ulonglong2* o = &g_rbf[(size_t)e * 10];
#pragma unroll
    for (int r2 = 0; r2 < 10; ++r2) o[r2] = buf[r2];
    g_sfc[e] = fc;
}

// ---------------- tiled fp32 GEMM with packed f32x2 micro-kernel ----------------
__global__ __launch_bounds__(128) void gemm_kernel(
    const float* __restrict__ Aext, const float* __restrict__ B,
    const float* __restrict__ bias, int M, int Ncols, int K, int mode)
{
    const float* __restrict__ A = (mode == 0) ? Aext : (const float*)g_T;
    float* C = (mode == 0) ? g_T : g_phi;

    __shared__ __align__(16) float As[16][64];
    __shared__ __align__(16) float Bs[16][64];

    int tid = threadIdx.x;
    int m0 = blockIdx.x * 64;
    int n0 = blockIdx.y * 64;
    int tr = tid >> 4;
    int tc = tid & 15;

    ull acc2[4][4];
#pragma unroll
    for (int i = 0; i < 4; ++i)
#pragma unroll
        for (int j = 0; j < 4; ++j) acc2[i][j] = 0ull;

    for (int kt = 0; kt < K; kt += 16) {
#pragma unroll
        for (int l = 0; l < 2; ++l) {
            int q = tid + l * 128;
            int row = q >> 2;
            int kc = (q & 3) * 4;
            float4 av = make_float4(0.f, 0.f, 0.f, 0.f);
            int gm = m0 + row;
            if (gm < M) av = *(const float4*)&A[(size_t)gm * K + kt + kc];
            As[kc + 0][row] = av.x; As[kc + 1][row] = av.y;
            As[kc + 2][row] = av.z; As[kc + 3][row] = av.w;
        }
#pragma unroll
        for (int l = 0; l < 2; ++l) {
            int q = tid + l * 128;
            int row = q >> 4;
            int cc = (q & 15) * 4;
            *(float4*)&Bs[row][cc] = *(const float4*)&B[(size_t)(kt + row) * Ncols + n0 + cc];
        }
        __syncthreads();
#pragma unroll
        for (int k = 0; k < 16; ++k) {
            ull aa[4];
#pragma unroll
            for (int i = 0; i < 4; ++i)
                aa[i] = *(const ull*)&As[k][tr * 8 + i * 2];
            float b[4];
            *(float4*)&b[0] = *(const float4*)&Bs[k][tc * 4];
#pragma unroll
            for (int j = 0; j < 4; ++j) {
                ull bv = pk2(b[j], b[j]);
#pragma unroll
                for (int i = 0; i < 4; ++i)
                    acc2[i][j] = ffma2(aa[i], bv, acc2[i][j]);
            }
        }
        __syncthreads();
    }

    float bv[4];
    *(float4*)bv = *(const float4*)&bias[n0 + tc * 4];
#pragma unroll
    for (int i2 = 0; i2 < 4; ++i2) {
        float2 c0 = upk2(acc2[i2][0]), c1 = upk2(acc2[i2][1]);
        float2 c2 = upk2(acc2[i2][2]), c3 = upk2(acc2[i2][3]);
        float4 row0 = make_float4(c0.x + bv[0], c1.x + bv[1], c2.x + bv[2], c3.x + bv[3]);
        float4 row1 = make_float4(c0.y + bv[0], c1.y + bv[1], c2.y + bv[2], c3.y + bv[3]);
        if (mode == 0) {
            row0.x = row0.x / (1.0f + __expf(-row0.x));
            row0.y = row0.y / (1.0f + __expf(-row0.y));
            row0.z = row0.z / (1.0f + __expf(-row0.z));
            row0.w = row0.w / (1.0f + __expf(-row0.w));
            row1.x = row1.x / (1.0f + __expf(-row1.x));
            row1.y = row1.y / (1.0f + __expf(-row1.y));
            row1.z = row1.z / (1.0f + __expf(-row1.z));
            row1.w = row1.w / (1.0f + __expf(-row1.w));
        }
        int gm0 = m0 + tr * 8 + i2 * 2;
        if (gm0 < M)     *(float4*)&C[(size_t)gm0 * Ncols + n0 + tc * 4] = row0;
        if (gm0 + 1 < M) *(float4*)&C[(size_t)(gm0 + 1) * Ncols + n0 + tc * 4] = row1;
    }
}

// ---------------- gather node kernel ----------------
// 128 threads = 2 edge-slots x 64 threads; thread t owns features (2t, 2t+1).
// RBF scalars preloaded per-edge from g_rbf (warp-uniform broadcast loads).
__global__ __launch_bounds__(128) void node_kernel(
    const float* __restrict__ v_i,
    const float* __restrict__ Wr, const float* __restrict__ br,
    float* __restrict__ out, int Nn)
{
    int tid = threadIdx.x;
    int sub = tid >> 6;       // edge-slot 0/1
    int t = tid & 63;
    int f0 = t * 2;

    ull W0[NRBF], W1r[NRBF], W2r[NRBF];
#pragma unroll
    for (int r = 0; r < NRBF; ++r) {
        W0[r]  = *(const ull*)&Wr[(size_t)r * PHI_COLS + 0 * FDIM + f0];
        W1r[r] = *(const ull*)&Wr[(size_t)r * PHI_COLS + 1 * FDIM + f0];
        W2r[r] = *(const ull*)&Wr[(size_t)r * PHI_COLS + 2 * FDIM + f0];
    }
    ull B0 = *(const ull*)&br[0 * FDIM + f0];
    ull B1 = *(const ull*)&br[1 * FDIM + f0];
    ull B2 = *(const ull*)&br[2 * FDIM + f0];

    __shared__ float sh[64 * 8];

    for (int nn = 0; nn < NPB; ++nn) {
        int n = blockIdx.x * NPB + nn;
        if (n >= Nn) break;

        int beg = g_off[n];
        int deg = g_deg[n];

        ull dh = 0ull, dva = 0ull, dvb = 0ull, dvc = 0ull;

        // pipeline stage regs (phi / v / u / fcut / pos)
        ull c_p0 = 0, c_p1 = 0, c_p2 = 0, c_v0 = 0, c_v1 = 0, c_v2 = 0;
        float c_u0 = 0, c_u1 = 0, c_u2 = 0, c_fc = 0;
        int c_pos = 0;

        if (sub < deg) {
            int pos = beg + sub;
            c_pos = pos;
            int src = g_srcs[pos];
            c_fc = g_sfc[pos];
            c_u0 = g_su[3 * (size_t)pos + 0];
            c_u1 = g_su[3 * (size_t)pos + 1];
            c_u2 = g_su[3 * (size_t)pos + 2];
            const float* pb = &g_phi[(size_t)src * PHI_COLS + f0];
            c_p0 = *(const ull*)(pb);
            c_p1 = *(const ull*)(pb + FDIM);
            c_p2 = *(const ull*)(pb + 2 * FDIM);
            const float* vb = &v_i[(size_t)src * (FDIM * 3) + (size_t)f0 * 3];
            c_v0 = pk2(vb[0], vb[3]);
            c_v1 = pk2(vb[1], vb[4]);
            c_v2 = pk2(vb[2], vb[5]);
        }

        for (int j = sub; j < deg; j += 2) {
            ull p0 = c_p0, p1 = c_p1, p2 = c_p2;
            ull vk0 = c_v0, vk1 = c_v1, vk2 = c_v2;
            float u0 = c_u0, u1 = c_u1, u2 = c_u2, fc = c_fc;
            int pos_cur = c_pos;

            int jn = j + 2;
            if (jn < deg) {
                int pos = beg + jn;
                c_pos = pos;
                int src = g_srcs[pos];
                c_fc = g_sfc[pos];
                c_u0 = g_su[3 * (size_t)pos + 0];
                c_u1 = g_su[3 * (size_t)pos + 1];
                c_u2 = g_su[3 * (size_t)pos + 2];
                const float* pb = &g_phi[(size_t)src * PHI_COLS + f0];
                c_p0 = *(const ull*)(pb);
                c_p1 = *(const ull*)(pb + FDIM);
                c_p2 = *(const ull*)(pb + 2 * FDIM);
                const float* vb = &v_i[(size_t)src * (FDIM * 3) + (size_t)f0 * 3];
                c_v0 = pk2(vb[0], vb[3]);
                c_v1 = pk2(vb[1], vb[4]);
                c_v2 = pk2(vb[2], vb[5]);
            }

            // RBF matvec: t-pairs are warp-uniform broadcast loads (MLP=10)
            const ulonglong2* __restrict__ tp = &g_rbf[(size_t)pos_cur * 10];
            ull a0 = 0ull, a1 = 0ull, a2 = 0ull;
#pragma unroll
            for (int r2 = 0; r2 < 10; ++r2) {
                ulonglong2 t2 = tp[r2];
                a0 = ffma2(t2.x, W0[2 * r2], a0);
                a1 = ffma2(t2.x, W1r[2 * r2], a1);
                a2 = ffma2(t2.x, W2r[2 * r2], a2);
                a0 = ffma2(t2.y, W0[2 * r2 + 1], a0);
                a1 = ffma2(t2.y, W1r[2 * r2 + 1], a1);
                a2 = ffma2(t2.y, W2r[2 * r2 + 1], a2);
            }
            ull fcv = pk2(fc, fc);
            ull e0 = ffma2(B0, fcv, a0);
            ull e1 = ffma2(B1, fcv, a1);
            ull e2 = ffma2(B2, fcv, a2);

            ull gm0 = fmul2(p0, e0);
            ull gm1 = fmul2(p1, e1);
            ull gm2 = fmul2(p2, e2);

            dh = fadd2(dh, gm2);
            dva = ffma2(gm0, pk2(u0, u0), ffma2(gm1, vk0, dva));
            dvb = ffma2(gm0, pk2(u1, u1), ffma2(gm1, vk1, dvb));
            dvc = ffma2(gm0, pk2(u2, u2), ffma2(gm1, vk2, dvc));
        }

        if (sub == 1) {
            float2 h = upk2(dh), a = upk2(dva), b = upk2(dvb), cc = upk2(dvc);
            float* p = &sh[t * 8];
            p[0] = h.x; p[1] = h.y; p[2] = a.x; p[3] = a.y;
            p[4] = b.x; p[5] = b.y; p[6] = cc.x; p[7] = cc.y;
        }
        __syncthreads();
        if (sub == 0) {
            float2 h = upk2(dh), a = upk2(dva), b = upk2(dvb), cc = upk2(dvc);
            const float* p = &sh[t * 8];
            h.x += p[0]; h.y += p[1]; a.x += p[2]; a.y += p[3];
            b.x += p[4]; b.y += p[5]; cc.x += p[6]; cc.y += p[7];

            *(float2*)&out[(size_t)n * FDIM + f0] = make_float2(h.x, h.y);
            float* od = out + (size_t)Nn * FDIM + (size_t)n * (FDIM * 3) + (size_t)f0 * 3;
            *(float2*)&od[0] = make_float2(a.x, b.x);
            *(float2*)&od[2] = make_float2(cc.x, a.y);
            *(float2*)&od[4] = make_float2(b.y, cc.y);
        }
        __syncthreads();
    }
}

// ---------------- launch ----------------
extern "C" void kernel_launch(void* const* d_in, const int* in_sizes, int n_in,
                              void* d_out, int out_size) {
    const float* h_i    = (const float*)d_in[0];
    const float* v_i    = (const float*)d_in[1];
    const float* d_ij   = (const float*)d_in[2];
    const float* unit_r = (const float*)d_in[3];
    const void*  nbrs   = (const void*)d_in[4];
    const float* W1     = (const float*)d_in[5];
    const float* b1     = (const float*)d_in[6];
    const float* W2     = (const float*)d_in[7];
    const float* b2     = (const float*)d_in[8];
    const float* Wr     = (const float*)d_in[9];
    const float* br     = (const float*)d_in[10];
    float* out = (float*)d_out;

    int N = in_sizes[0] / FDIM;
    int E = in_sizes[2];

    init_kernel<<<(N + 255) / 256, 256>>>((const int*)nbrs, in_sizes[4], N);
    hist_kernel<<<(E + 255) / 256, 256>>>(nbrs, E);
    scan_kernel<<<1, 1024>>>(N);
    scatter_kernel<<<(E + 255) / 256, 256>>>(nbrs, d_ij, unit_r, E);
    rbf_kernel<<<(E + 255) / 256, 256>>>(E);

    gemm_kernel<<<dim3((N + 63) / 64, 2), 128>>>(h_i, W1, b1, N, FDIM, FDIM, 0);
    gemm_kernel<<<dim3((N + 63) / 64, 6), 128>>>(nullptr, W2, b2, N, PHI_COLS, FDIM, 1);

    node_kernel<<<(N + NPB - 1) / NPB, 128>>>(v_i, Wr, br, out, N);
}

// round 7
// speedup vs baseline: 1.2990x; 1.2990x over previous
#include <cuda_runtime.h>

#define NMAX 20000
#define EMAX 320000
#define FDIM 128
#define PHI_COLS 384
#define NRBF 20
#define NPB 4   // nodes per block in the gather kernel

typedef unsigned long long ull;

// ---------------- scratch (static __device__, no allocations) ----------------
__device__ __align__(16) float g_T[(size_t)NMAX * FDIM];        // silu(h@W1+b1)
__device__ __align__(16) float g_phi[(size_t)NMAX * PHI_COLS];  // phi
__device__ int   g_deg[NMAX];
__device__ int   g_off[NMAX];
__device__ int   g_cur[NMAX];
__device__ int   g_srcs[EMAX];              // sorted-by-dst: src node id
__device__ float g_sd[EMAX];                // sorted-by-dst: d_ij
__device__ __align__(16) float g_su[(size_t)3 * EMAX];          // sorted-by-dst: unit_r
__device__ int   g_is64;   // 1 if nbrs is int64 pairs, 0 if int32 pairs

// ---------------- packed f32x2 helpers (sm_103a) ----------------
__device__ __forceinline__ ull pk2(float x, float y) {
    ull r; asm("mov.b64 %0, {%1, %2};" : "=l"(r) : "f"(x), "f"(y)); return r;
}
__device__ __forceinline__ float2 upk2(ull a) {
    float2 r; asm("mov.b64 {%0, %1}, %2;" : "=f"(r.x), "=f"(r.y) : "l"(a)); return r;
}
__device__ __forceinline__ ull ffma2(ull a, ull b, ull c) {
    ull d; asm("fma.rn.f32x2 %0, %1, %2, %3;" : "=l"(d) : "l"(a), "l"(b), "l"(c)); return d;
}
__device__ __forceinline__ ull fmul2(ull a, ull b) {
    ull d; asm("mul.rn.f32x2 %0, %1, %2;" : "=l"(d) : "l"(a), "l"(b)); return d;
}
__device__ __forceinline__ ull fadd2(ull a, ull b) {
    ull d; asm("add.rn.f32x2 %0, %1, %2;" : "=l"(d) : "l"(a), "l"(b)); return d;
}

__device__ __forceinline__ int2 edge_pair(const void* __restrict__ nbrs, size_t e, int is64) {
    if (is64) {
        const long long* p = (const long long*)nbrs;
        return make_int2((int)p[2 * e], (int)p[2 * e + 1]);
    } else {
        return ((const int2*)nbrs)[e];
    }
}

// ---------------- fused init: zero degrees + nbrs dtype detect ----------------
__global__ void init_kernel(const int* __restrict__ w, int nwords, int Nn) {
    int i = blockIdx.x * 256 + threadIdx.x;
    if (i < Nn) g_deg[i] = 0;
    if (i == 0) {
        int any = 0;
        int lim = nwords < 32 ? nwords : 32;
        for (int k = 1; k < lim; k += 2) any |= w[k];
        g_is64 = (any == 0) ? 1 : 0;
    }
}

__global__ void hist_kernel(const void* __restrict__ nbrs, int E) {
    int is64 = g_is64;
    int e = blockIdx.x * 256 + threadIdx.x;
    if (e < E) {
        int2 p = edge_pair(nbrs, (size_t)e, is64);
        atomicAdd(&g_deg[p.x], 1);
    }
}

// single block, 1024 threads, 20 elems/thread compile-time unrolled, chunked by 20480
__global__ void scan_kernel(int Nn) {
    __shared__ int warpsum[32];
    int t = threadIdx.x, lane = t & 31, w = t >> 5;
    int run = 0;
    for (int base = 0; base < Nn; base += 20480) {
        int vals[20];
        int s = 0;
        int i0 = base + t * 20;
#pragma unroll
        for (int k = 0; k < 20; ++k) {
            int i = i0 + k;
            int v = (i < Nn) ? g_deg[i] : 0;
            vals[k] = s;
            s += v;
        }
        int x = s;
#pragma unroll
        for (int off = 1; off < 32; off <<= 1) {
            int y = __shfl_up_sync(0xFFFFFFFFu, x, off);
            if (lane >= off) x += y;
        }
        if (lane == 31) warpsum[w] = x;
        __syncthreads();
        if (w == 0) {
            int y = warpsum[lane];
#pragma unroll
            for (int off = 1; off < 32; off <<= 1) {
                int z = __shfl_up_sync(0xFFFFFFFFu, y, off);
                if (lane >= off) y += z;
            }
            warpsum[lane] = y;
        }
        __syncthreads();
        int excl = run + x - s + ((w > 0) ? warpsum[w - 1] : 0);
#pragma unroll
        for (int k = 0; k < 20; ++k) {
            int i = i0 + k;
            if (i < Nn) { g_off[i] = excl + vals[k]; g_cur[i] = excl + vals[k]; }
        }
        run += warpsum[31];
        __syncthreads();
    }
}

// scatter edges into dst-sorted arrays (src, d, unit_r)
__global__ void scatter_kernel(const void* __restrict__ nbrs,
                               const float* __restrict__ d_ij,
                               const float* __restrict__ ur, int E) {
    int is64 = g_is64;
    int e = blockIdx.x * 256 + threadIdx.x;
    if (e < E) {
        int2 p = edge_pair(nbrs, (size_t)e, is64);
        int pos = atomicAdd(&g_cur[p.x], 1);
        g_srcs[pos] = p.y;
        g_sd[pos] = d_ij[e];
        g_su[3 * (size_t)pos + 0] = ur[3 * (size_t)e + 0];
        g_su[3 * (size_t)pos + 1] = ur[3 * (size_t)e + 1];
        g_su[3 * (size_t)pos + 2] = ur[3 * (size_t)e + 2];
    }
}

// ---------------- tiled fp32 GEMM with packed f32x2 micro-kernel ----------------
__global__ __launch_bounds__(128) void gemm_kernel(
    const float* __restrict__ Aext, const float* __restrict__ B,
    const float* __restrict__ bias, int M, int Ncols, int K, int mode)
{
    const float* __restrict__ A = (mode == 0) ? Aext : (const float*)g_T;
    float* C = (mode == 0) ? g_T : g_phi;

    __shared__ __align__(16) float As[16][64];
    __shared__ __align__(16) float Bs[16][64];

    int tid = threadIdx.x;
    int m0 = blockIdx.x * 64;
    int n0 = blockIdx.y * 64;
    int tr = tid >> 4;
    int tc = tid & 15;

    ull acc2[4][4];
#pragma unroll
    for (int i = 0; i < 4; ++i)
#pragma unroll
        for (int j = 0; j < 4; ++j) acc2[i][j] = 0ull;

    for (int kt = 0; kt < K; kt += 16) {
#pragma unroll
        for (int l = 0; l < 2; ++l) {
            int q = tid + l * 128;
            int row = q >> 2;
            int kc = (q & 3) * 4;
            float4 av = make_float4(0.f, 0.f, 0.f, 0.f);
            int gm = m0 + row;
            if (gm < M) av = *(const float4*)&A[(size_t)gm * K + kt + kc];
            As[kc + 0][row] = av.x; As[kc + 1][row] = av.y;
            As[kc + 2][row] = av.z; As[kc + 3][row] = av.w;
        }
#pragma unroll
        for (int l = 0; l < 2; ++l) {
            int q = tid + l * 128;
            int row = q >> 4;
            int cc = (q & 15) * 4;
            *(float4*)&Bs[row][cc] = *(const float4*)&B[(size_t)(kt + row) * Ncols + n0 + cc];
        }
        __syncthreads();
#pragma unroll
        for (int k = 0; k < 16; ++k) {
            ull aa[4];
#pragma unroll
            for (int i = 0; i < 4; ++i)
                aa[i] = *(const ull*)&As[k][tr * 8 + i * 2];
            float b[4];
            *(float4*)&b[0] = *(const float4*)&Bs[k][tc * 4];
#pragma unroll
            for (int j = 0; j < 4; ++j) {
                ull bv = pk2(b[j], b[j]);
#pragma unroll
                for (int i = 0; i < 4; ++i)
                    acc2[i][j] = ffma2(aa[i], bv, acc2[i][j]);
            }
        }
        __syncthreads();
    }

    float bv[4];
    *(float4*)bv = *(const float4*)&bias[n0 + tc * 4];
#pragma unroll
    for (int i2 = 0; i2 < 4; ++i2) {
        float2 c0 = upk2(acc2[i2][0]), c1 = upk2(acc2[i2][1]);
        float2 c2 = upk2(acc2[i2][2]), c3 = upk2(acc2[i2][3]);
        float4 row0 = make_float4(c0.x + bv[0], c1.x + bv[1], c2.x + bv[2], c3.x + bv[3]);
        float4 row1 = make_float4(c0.y + bv[0], c1.y + bv[1], c2.y + bv[2], c3.y + bv[3]);
        if (mode == 0) {
            row0.x = row0.x / (1.0f + __expf(-row0.x));
            row0.y = row0.y / (1.0f + __expf(-row0.y));
            row0.z = row0.z / (1.0f + __expf(-row0.z));
            row0.w = row0.w / (1.0f + __expf(-row0.w));
            row1.x = row1.x / (1.0f + __expf(-row1.x));
            row1.y = row1.y / (1.0f + __expf(-row1.y));
            row1.z = row1.z / (1.0f + __expf(-row1.z));
            row1.w = row1.w / (1.0f + __expf(-row1.w));
        }
        int gm0 = m0 + tr * 8 + i2 * 2;
        if (gm0 < M)     *(float4*)&C[(size_t)gm0 * Ncols + n0 + tc * 4] = row0;
        if (gm0 + 1 < M) *(float4*)&C[(size_t)(gm0 + 1) * Ncols + n0 + tc * 4] = row1;
    }
}

// ---------------- gather node kernel (2-stage software pipeline) ----------------
// 128 threads = 2 edge-slots x 64 threads; thread t owns features (2t, 2t+1).
__global__ __launch_bounds__(128) void node_kernel(
    const float* __restrict__ v_i,
    const float* __restrict__ Wr, const float* __restrict__ br,
    float* __restrict__ out, int Nn)
{
    int tid = threadIdx.x;
    int sub = tid >> 6;       // edge-slot 0/1
    int t = tid & 63;
    int f0 = t * 2;           // features f0, f0+1

    ull W0[NRBF], W1r[NRBF], W2r[NRBF];
#pragma unroll
    for (int r = 0; r < NRBF; ++r) {
        W0[r]  = *(const ull*)&Wr[(size_t)r * PHI_COLS + 0 * FDIM + f0];
        W1r[r] = *(const ull*)&Wr[(size_t)r * PHI_COLS + 1 * FDIM + f0];
        W2r[r] = *(const ull*)&Wr[(size_t)r * PHI_COLS + 2 * FDIM + f0];
    }
    ull B0 = *(const ull*)&br[0 * FDIM + f0];
    ull B1 = *(const ull*)&br[1 * FDIM + f0];
    ull B2 = *(const ull*)&br[2 * FDIM + f0];

    __shared__ float sh[64 * 8];

    for (int nn = 0; nn < NPB; ++nn) {
        int n = blockIdx.x * NPB + nn;
        if (n >= Nn) break;

        int beg = g_off[n];
        int deg = g_deg[n];

        ull dh = 0ull, dva = 0ull, dvb = 0ull, dvc = 0ull;

        // pipeline stage registers
        ull c_p0 = 0, c_p1 = 0, c_p2 = 0, c_v0 = 0, c_v1 = 0, c_v2 = 0;
        float c_d = 1.0f, c_u0 = 0, c_u1 = 0, c_u2 = 0;

        // prologue: load edge 'sub'
        if (sub < deg) {
            int pos = beg + sub;
            int src = g_srcs[pos];
            c_d = g_sd[pos];
            c_u0 = g_su[3 * (size_t)pos + 0];
            c_u1 = g_su[3 * (size_t)pos + 1];
            c_u2 = g_su[3 * (size_t)pos + 2];
            const float* pb = &g_phi[(size_t)src * PHI_COLS + f0];
            c_p0 = *(const ull*)(pb);
            c_p1 = *(const ull*)(pb + FDIM);
            c_p2 = *(const ull*)(pb + 2 * FDIM);
            // v_i features (f0, f0+1): 24 contiguous bytes, 8B-aligned -> 3x LDG.64
            const float2* vb2 = (const float2*)&v_i[(size_t)src * (FDIM * 3) + (size_t)f0 * 3];
            float2 va = vb2[0], vb = vb2[1], vc = vb2[2];
            c_v0 = pk2(va.x, vb.y);
            c_v1 = pk2(va.y, vc.x);
            c_v2 = pk2(vb.x, vc.y);
        }

        for (int j = sub; j < deg; j += 2) {
            // capture current stage
            ull p0 = c_p0, p1 = c_p1, p2 = c_p2;
            ull vk0 = c_v0, vk1 = c_v1, vk2 = c_v2;
            float d = c_d, u0 = c_u0, u1 = c_u1, u2 = c_u2;

            // issue next stage loads (overlap with compute below)
            int jn = j + 2;
            if (jn < deg) {
                int pos = beg + jn;
                int src = g_srcs[pos];
                c_d = g_sd[pos];
                c_u0 = g_su[3 * (size_t)pos + 0];
                c_u1 = g_su[3 * (size_t)pos + 1];
                c_u2 = g_su[3 * (size_t)pos + 2];
                const float* pb = &g_phi[(size_t)src * PHI_COLS + f0];
                c_p0 = *(const ull*)(pb);
                c_p1 = *(const ull*)(pb + FDIM);
                c_p2 = *(const ull*)(pb + 2 * FDIM);
                const float2* vb2 = (const float2*)&v_i[(size_t)src * (FDIM * 3) + (size_t)f0 * 3];
                float2 va = vb2[0], vb = vb2[1], vc = vb2[2];
                c_v0 = pk2(va.x, vb.y);
                c_v1 = pk2(va.y, vc.x);
                c_v2 = pk2(vb.x, vc.y);
            }

            float x = d * 0.62831853071795864769f;  // pi/5
            float s, c;
            __sincosf(x, &s, &c);
            float fcs = (d < 5.0f) ? 0.5f * (c + 1.0f) : 0.0f;
            float invd = __frcp_rn(d);
            float twoc = c + c;

            ull a0 = 0ull, a1 = 0ull, a2 = 0ull;
            float sp = 0.0f, sn = s;
#pragma unroll
            for (int r = 0; r < NRBF; ++r) {
                ull sv = pk2(sn, sn);
                a0 = ffma2(sv, W0[r], a0);
                a1 = ffma2(sv, W1r[r], a1);
                a2 = ffma2(sv, W2r[r], a2);
                float s2 = __fmaf_rn(twoc, sn, -sp);
                sp = sn; sn = s2;
            }

            ull invdv = pk2(invd, invd);
            ull fcv = pk2(fcs, fcs);
            ull e0 = fmul2(ffma2(a0, invdv, B0), fcv);
            ull e1 = fmul2(ffma2(a1, invdv, B1), fcv);
            ull e2 = fmul2(ffma2(a2, invdv, B2), fcv);

            ull gm0 = fmul2(p0, e0);
            ull gm1 = fmul2(p1, e1);
            ull gm2 = fmul2(p2, e2);

            dh = fadd2(dh, gm2);
            dva = ffma2(gm0, pk2(u0, u0), ffma2(gm1, vk0, dva));
            dvb = ffma2(gm0, pk2(u1, u1), ffma2(gm1, vk1, dvb));
            dvc = ffma2(gm0, pk2(u2, u2), ffma2(gm1, vk2, dvc));
        }

        if (sub == 1) {
            float2 h = upk2(dh), a = upk2(dva), b = upk2(dvb), cc = upk2(dvc);
            float* p = &sh[t * 8];
            p[0] = h.x; p[1] = h.y; p[2] = a.x; p[3] = a.y;
            p[4] = b.x; p[5] = b.y; p[6] = cc.x; p[7] = cc.y;
        }
        __syncthreads();
        if (sub == 0) {
            float2 h = upk2(dh), a = upk2(dva), b = upk2(dvb), cc = upk2(dvc);
            const float* p = &sh[t * 8];
            h.x += p[0]; h.y += p[1]; a.x += p[2]; a.y += p[3];
            b.x += p[4]; b.y += p[5]; cc.x += p[6]; cc.y += p[7];

            *(float2*)&out[(size_t)n * FDIM + f0] = make_float2(h.x, h.y);
            float* od = out + (size_t)Nn * FDIM + (size_t)n * (FDIM * 3) + (size_t)f0 * 3;
            *(float2*)&od[0] = make_float2(a.x, b.x);
            *(float2*)&od[2] = make_float2(cc.x, a.y);
            *(float2*)&od[4] = make_float2(b.y, cc.y);
        }
        __syncthreads();
    }
}

// ---------------- launch ----------------
extern "C" void kernel_launch(void* const* d_in, const int* in_sizes, int n_in,
                              void* d_out, int out_size) {
    const float* h_i    = (const float*)d_in[0];
    const float* v_i    = (const float*)d_in[1];
    const float* d_ij   = (const float*)d_in[2];
    const float* unit_r = (const float*)d_in[3];
    const void*  nbrs   = (const void*)d_in[4];
    const float* W1     = (const float*)d_in[5];
    const float* b1     = (const float*)d_in[6];
    const float* W2     = (const float*)d_in[7];
    const float* b2     = (const float*)d_in[8];
    const float* Wr     = (const float*)d_in[9];
    const float* br     = (const float*)d_in[10];
    float* out = (float*)d_out;

    int N = in_sizes[0] / FDIM;
    int E = in_sizes[2];

    init_kernel<<<(N + 255) / 256, 256>>>((const int*)nbrs, in_sizes[4], N);
    hist_kernel<<<(E + 255) / 256, 256>>>(nbrs, E);
    scan_kernel<<<1, 1024>>>(N);
    scatter_kernel<<<(E + 255) / 256, 256>>>(nbrs, d_ij, unit_r, E);

    gemm_kernel<<<dim3((N + 63) / 64, 2), 128>>>(h_i, W1, b1, N, FDIM, FDIM, 0);
    gemm_kernel<<<dim3((N + 63) / 64, 6), 128>>>(nullptr, W2, b2, N, PHI_COLS, FDIM, 1);

    node_kernel<<<(N + NPB - 1) / NPB, 128>>>(v_i, Wr, br, out, N);
}

// round 11
// speedup vs baseline: 1.3096x; 1.0082x over previous
#include <cuda_runtime.h>

#define NMAX 20000
#define EMAX 320000
#define FDIM 128
#define PHI_COLS 384
#define NRBF 20
#define NPB 4   // nodes per block in the gather kernel

typedef unsigned long long ull;

// ---------------- scratch (static __device__, no allocations) ----------------
__device__ __align__(16) float g_T[(size_t)NMAX * FDIM];        // silu(h@W1+b1)
__device__ __align__(16) float g_phi[(size_t)NMAX * PHI_COLS];  // phi
__device__ int   g_deg[NMAX];
__device__ int   g_off[NMAX];
__device__ int   g_cur[NMAX];
__device__ int   g_srcs[EMAX];              // sorted-by-dst: src node id
__device__ float g_sd[EMAX];                // sorted-by-dst: d_ij
__device__ __align__(16) float g_su[(size_t)3 * EMAX];          // sorted-by-dst: unit_r
__device__ int   g_is64;   // 1 if nbrs is int64 pairs, 0 if int32 pairs

// ---------------- packed f32x2 helpers (sm_103a) ----------------
__device__ __forceinline__ ull pk2(float x, float y) {
    ull r; asm("mov.b64 %0, {%1, %2};" : "=l"(r) : "f"(x), "f"(y)); return r;
}
__device__ __forceinline__ float2 upk2(ull a) {
    float2 r; asm("mov.b64 {%0, %1}, %2;" : "=f"(r.x), "=f"(r.y) : "l"(a)); return r;
}
__device__ __forceinline__ ull ffma2(ull a, ull b, ull c) {
    ull d; asm("fma.rn.f32x2 %0, %1, %2, %3;" : "=l"(d) : "l"(a), "l"(b), "l"(c)); return d;
}
__device__ __forceinline__ ull fmul2(ull a, ull b) {
    ull d; asm("mul.rn.f32x2 %0, %1, %2;" : "=l"(d) : "l"(a), "l"(b)); return d;
}
__device__ __forceinline__ ull fadd2(ull a, ull b) {
    ull d; asm("add.rn.f32x2 %0, %1, %2;" : "=l"(d) : "l"(a), "l"(b)); return d;
}

__device__ __forceinline__ int2 edge_pair(const void* __restrict__ nbrs, size_t e, int is64) {
    if (is64) {
        const long long* p = (const long long*)nbrs;
        return make_int2((int)p[2 * e], (int)p[2 * e + 1]);
    } else {
        return ((const int2*)nbrs)[e];
    }
}

// ---------------- fused init: zero degrees + nbrs dtype detect ----------------
__global__ void init_kernel(const int* __restrict__ w, int nwords, int Nn) {
    int i = blockIdx.x * 256 + threadIdx.x;
    if (i < Nn) g_deg[i] = 0;
    if (i == 0) {
        int any = 0;
        int lim = nwords < 32 ? nwords : 32;
        for (int k = 1; k < lim; k += 2) any |= w[k];
        g_is64 = (any == 0) ? 1 : 0;
    }
}

__global__ void hist_kernel(const void* __restrict__ nbrs, int E) {
    int is64 = g_is64;
    int e = blockIdx.x * 256 + threadIdx.x;
    if (e < E) {
        int2 p = edge_pair(nbrs, (size_t)e, is64);
        atomicAdd(&g_deg[p.x], 1);
    }
}

// single block, 1024 threads, 20 elems/thread compile-time unrolled, chunked by 20480
__global__ void scan_kernel(int Nn) {
    __shared__ int warpsum[32];
    int t = threadIdx.x, lane = t & 31, w = t >> 5;
    int run = 0;
    for (int base = 0; base < Nn; base += 20480) {
        int vals[20];
        int s = 0;
        int i0 = base + t * 20;
#pragma unroll
        for (int k = 0; k < 20; ++k) {
            int i = i0 + k;
            int v = (i < Nn) ? g_deg[i] : 0;
            vals[k] = s;
            s += v;
        }
        int x = s;
#pragma unroll
        for (int off = 1; off < 32; off <<= 1) {
            int y = __shfl_up_sync(0xFFFFFFFFu, x, off);
            if (lane >= off) x += y;
        }
        if (lane == 31) warpsum[w] = x;
        __syncthreads();
        if (w == 0) {
            int y = warpsum[lane];
#pragma unroll
            for (int off = 1; off < 32; off <<= 1) {
                int z = __shfl_up_sync(0xFFFFFFFFu, y, off);
                if (lane >= off) y += z;
            }
            warpsum[lane] = y;
        }
        __syncthreads();
        int excl = run + x - s + ((w > 0) ? warpsum[w - 1] : 0);
#pragma unroll
        for (int k = 0; k < 20; ++k) {
            int i = i0 + k;
            if (i < Nn) { g_off[i] = excl + vals[k]; g_cur[i] = excl + vals[k]; }
        }
        run += warpsum[31];
        __syncthreads();
    }
}

// scatter edges into dst-sorted arrays (src, d, unit_r)
__global__ void scatter_kernel(const void* __restrict__ nbrs,
                               const float* __restrict__ d_ij,
                               const float* __restrict__ ur, int E) {
    int is64 = g_is64;
    int e = blockIdx.x * 256 + threadIdx.x;
    if (e < E) {
        int2 p = edge_pair(nbrs, (size_t)e, is64);
        int pos = atomicAdd(&g_cur[p.x], 1);
        g_srcs[pos] = p.y;
        g_sd[pos] = d_ij[e];
        g_su[3 * (size_t)pos + 0] = ur[3 * (size_t)e + 0];
        g_su[3 * (size_t)pos + 1] = ur[3 * (size_t)e + 1];
        g_su[3 * (size_t)pos + 2] = ur[3 * (size_t)e + 2];
    }
}

// ---------------- tiled fp32 GEMM with packed f32x2 micro-kernel ----------------
__global__ __launch_bounds__(128) void gemm_kernel(
    const float* __restrict__ Aext, const float* __restrict__ B,
    const float* __restrict__ bias, int M, int Ncols, int K, int mode)
{
    const float* __restrict__ A = (mode == 0) ? Aext : (const float*)g_T;
    float* C = (mode == 0) ? g_T : g_phi;

    __shared__ __align__(16) float As[16][64];
    __shared__ __align__(16) float Bs[16][64];

    int tid = threadIdx.x;
    int m0 = blockIdx.x * 64;
    int n0 = blockIdx.y * 64;
    int tr = tid >> 4;
    int tc = tid & 15;

    ull acc2[4][4];
#pragma unroll
    for (int i = 0; i < 4; ++i)
#pragma unroll
        for (int j = 0; j < 4; ++j) acc2[i][j] = 0ull;

    for (int kt = 0; kt < K; kt += 16) {
#pragma unroll
        for (int l = 0; l < 2; ++l) {
            int q = tid + l * 128;
            int row = q >> 2;
            int kc = (q & 3) * 4;
            float4 av = make_float4(0.f, 0.f, 0.f, 0.f);
            int gm = m0 + row;
            if (gm < M) av = *(const float4*)&A[(size_t)gm * K + kt + kc];
            As[kc + 0][row] = av.x; As[kc + 1][row] = av.y;
            As[kc + 2][row] = av.z; As[kc + 3][row] = av.w;
        }
#pragma unroll
        for (int l = 0; l < 2; ++l) {
            int q = tid + l * 128;
            int row = q >> 4;
            int cc = (q & 15) * 4;
            *(float4*)&Bs[row][cc] = *(const float4*)&B[(size_t)(kt + row) * Ncols + n0 + cc];
        }
        __syncthreads();
#pragma unroll
        for (int k = 0; k < 16; ++k) {
            ull aa[4];
#pragma unroll
            for (int i = 0; i < 4; ++i)
                aa[i] = *(const ull*)&As[k][tr * 8 + i * 2];
            float b[4];
            *(float4*)&b[0] = *(const float4*)&Bs[k][tc * 4];
#pragma unroll
            for (int j = 0; j < 4; ++j) {
                ull bv = pk2(b[j], b[j]);
#pragma unroll
                for (int i = 0; i < 4; ++i)
                    acc2[i][j] = ffma2(aa[i], bv, acc2[i][j]);
            }
        }
        __syncthreads();
    }

    float bv[4];
    *(float4*)bv = *(const float4*)&bias[n0 + tc * 4];
#pragma unroll
    for (int i2 = 0; i2 < 4; ++i2) {
        float2 c0 = upk2(acc2[i2][0]), c1 = upk2(acc2[i2][1]);
        float2 c2 = upk2(acc2[i2][2]), c3 = upk2(acc2[i2][3]);
        float4 row0 = make_float4(c0.x + bv[0], c1.x + bv[1], c2.x + bv[2], c3.x + bv[3]);
        float4 row1 = make_float4(c0.y + bv[0], c1.y + bv[1], c2.y + bv[2], c3.y + bv[3]);
        if (mode == 0) {
            row0.x = row0.x / (1.0f + __expf(-row0.x));
            row0.y = row0.y / (1.0f + __expf(-row0.y));
            row0.z = row0.z / (1.0f + __expf(-row0.z));
            row0.w = row0.w / (1.0f + __expf(-row0.w));
            row1.x = row1.x / (1.0f + __expf(-row1.x));
            row1.y = row1.y / (1.0f + __expf(-row1.y));
            row1.z = row1.z / (1.0f + __expf(-row1.z));
            row1.w = row1.w / (1.0f + __expf(-row1.w));
        }
        int gm0 = m0 + tr * 8 + i2 * 2;
        if (gm0 < M)     *(float4*)&C[(size_t)gm0 * Ncols + n0 + tc * 4] = row0;
        if (gm0 + 1 < M) *(float4*)&C[(size_t)(gm0 + 1) * Ncols + n0 + tc * 4] = row1;
    }
}

// ---------------- gather node kernel (2-stage software pipeline) ----------------
// 128 threads = 2 edge-slots x 64 threads; thread t owns features (2t, 2t+1).
// Packed Chebyshev recurrence with sign-folded weights (ε pattern +,+,-,-,...):
//   w_r = ffma2(±2cos(x), w_{r-1}, w_{r-2}),  weights pre-multiplied by ε_r.
__global__ __launch_bounds__(128) void node_kernel(
    const float* __restrict__ v_i,
    const float* __restrict__ Wr, const float* __restrict__ br,
    float* __restrict__ out, int Nn)
{
    int tid = threadIdx.x;
    int sub = tid >> 6;       // edge-slot 0/1
    int t = tid & 63;
    int f0 = t * 2;           // features f0, f0+1

    // sign-folded weight registers: ε_r = + for r%4 in {0,1}, − for {2,3}
    ull W0[NRBF], W1r[NRBF], W2r[NRBF];
#pragma unroll
    for (int r = 0; r < NRBF; ++r) {
        float sg = (r & 2) ? -1.0f : 1.0f;
        const float* w0p = &Wr[(size_t)r * PHI_COLS + 0 * FDIM + f0];
        const float* w1p = &Wr[(size_t)r * PHI_COLS + 1 * FDIM + f0];
        const float* w2p = &Wr[(size_t)r * PHI_COLS + 2 * FDIM + f0];
        W0[r]  = pk2(sg * w0p[0], sg * w0p[1]);
        W1r[r] = pk2(sg * w1p[0], sg * w1p[1]);
        W2r[r] = pk2(sg * w2p[0], sg * w2p[1]);
    }
    ull B0 = *(const ull*)&br[0 * FDIM + f0];
    ull B1 = *(const ull*)&br[1 * FDIM + f0];
    ull B2 = *(const ull*)&br[2 * FDIM + f0];

    __shared__ float sh[64 * 8];

    for (int nn = 0; nn < NPB; ++nn) {
        int n = blockIdx.x * NPB + nn;
        if (n >= Nn) break;

        int beg = g_off[n];
        int deg = g_deg[n];

        ull dh = 0ull, dva = 0ull, dvb = 0ull, dvc = 0ull;

        // pipeline stage registers
        ull c_p0 = 0, c_p1 = 0, c_p2 = 0, c_v0 = 0, c_v1 = 0, c_v2 = 0;
        float c_d = 1.0f, c_u0 = 0, c_u1 = 0, c_u2 = 0;

        // prologue: load edge 'sub'
        if (sub < deg) {
            int pos = beg + sub;
            int src = g_srcs[pos];
            c_d = g_sd[pos];
            c_u0 = g_su[3 * (size_t)pos + 0];
            c_u1 = g_su[3 * (size_t)pos + 1];
            c_u2 = g_su[3 * (size_t)pos + 2];
            const float* pb = &g_phi[(size_t)src * PHI_COLS + f0];
            c_p0 = *(const ull*)(pb);
            c_p1 = *(const ull*)(pb + FDIM);
            c_p2 = *(const ull*)(pb + 2 * FDIM);
            const float* vb = &v_i[(size_t)src * (FDIM * 3) + (size_t)f0 * 3];
            c_v0 = pk2(vb[0], vb[3]);
            c_v1 = pk2(vb[1], vb[4]);
            c_v2 = pk2(vb[2], vb[5]);
        }

        for (int j = sub; j < deg; j += 2) {
            // capture current stage
            ull p0 = c_p0, p1 = c_p1, p2 = c_p2;
            ull vk0 = c_v0, vk1 = c_v1, vk2 = c_v2;
            float d = c_d, u0 = c_u0, u1 = c_u1, u2 = c_u2;

            // issue next stage loads (overlap with compute below)
            int jn = j + 2;
            if (jn < deg) {
                int pos = beg + jn;
                int src = g_srcs[pos];
                c_d = g_sd[pos];
                c_u0 = g_su[3 * (size_t)pos + 0];
                c_u1 = g_su[3 * (size_t)pos + 1];
                c_u2 = g_su[3 * (size_t)pos + 2];
                const float* pb = &g_phi[(size_t)src * PHI_COLS + f0];
                c_p0 = *(const ull*)(pb);
                c_p1 = *(const ull*)(pb + FDIM);
                c_p2 = *(const ull*)(pb + 2 * FDIM);
                const float* vb = &v_i[(size_t)src * (FDIM * 3) + (size_t)f0 * 3];
                c_v0 = pk2(vb[0], vb[3]);
                c_v1 = pk2(vb[1], vb[4]);
                c_v2 = pk2(vb[2], vb[5]);
            }

            float x = d * 0.62831853071795864769f;  // pi/5
            float s, c;
            __sincosf(x, &s, &c);
            float fcs = (d < 5.0f) ? 0.5f * (c + 1.0f) : 0.0f;
            float invd = __frcp_rn(d);
            float twoc = c + c;

            // packed sign-folded Chebyshev: w0 = (s,s); w1 = 2c*w0;
            // w_r = ffma2(cp/cm alternating, w_{r-1}, w_{r-2})
            ull cp = pk2(twoc, twoc);
            ull cm = pk2(-twoc, -twoc);
            ull wprev = pk2(s, s);        // r=0, ε=+
            ull wcur  = fmul2(cp, wprev); // r=1, ε=+ (sin2x dup)

            ull a0 = ffma2(wprev, W0[0], 0ull);
            ull a1 = ffma2(wprev, W1r[0], 0ull);
            ull a2 = ffma2(wprev, W2r[0], 0ull);
            a0 = ffma2(wcur, W0[1], a0);
            a1 = ffma2(wcur, W1r[1], a1);
            a2 = ffma2(wcur, W2r[1], a2);
#pragma unroll
            for (int r = 2; r < NRBF; ++r) {
                // ratio ε_r/ε_{r-1}: r even -> -, r odd -> +
                ull cc2 = (r & 1) ? cp : cm;
                ull wn = ffma2(cc2, wcur, wprev);
                wprev = wcur; wcur = wn;
                a0 = ffma2(wcur, W0[r], a0);
                a1 = ffma2(wcur, W1r[r], a1);
                a2 = ffma2(wcur, W2r[r], a2);
            }

            ull invdv = pk2(invd, invd);
            ull fcv = pk2(fcs, fcs);
            ull e0 = fmul2(ffma2(a0, invdv, B0), fcv);
            ull e1 = fmul2(ffma2(a1, invdv, B1), fcv);
            ull e2 = fmul2(ffma2(a2, invdv, B2), fcv);

            ull gm0 = fmul2(p0, e0);
            ull gm1 = fmul2(p1, e1);
            ull gm2 = fmul2(p2, e2);

            dh = fadd2(dh, gm2);
            dva = ffma2(gm0, pk2(u0, u0), ffma2(gm1, vk0, dva));
            dvb = ffma2(gm0, pk2(u1, u1), ffma2(gm1, vk1, dvb));
            dvc = ffma2(gm0, pk2(u2, u2), ffma2(gm1, vk2, dvc));
        }

        if (sub == 1) {
            float2 h = upk2(dh), a = upk2(dva), b = upk2(dvb), cc = upk2(dvc);
            float* p = &sh[t * 8];
            p[0] = h.x; p[1] = h.y; p[2] = a.x; p[3] = a.y;
            p[4] = b.x; p[5] = b.y; p[6] = cc.x; p[7] = cc.y;
        }
        __syncthreads();
        if (sub == 0) {
            float2 h = upk2(dh), a = upk2(dva), b = upk2(dvb), cc = upk2(dvc);
            const float* p = &sh[t * 8];
            h.x += p[0]; h.y += p[1]; a.x += p[2]; a.y += p[3];
            b.x += p[4]; b.y += p[5]; cc.x += p[6]; cc.y += p[7];

            *(float2*)&out[(size_t)n * FDIM + f0] = make_float2(h.x, h.y);
            float* od = out + (size_t)Nn * FDIM + (size_t)n * (FDIM * 3) + (size_t)f0 * 3;
            *(float2*)&od[0] = make_float2(a.x, b.x);
            *(float2*)&od[2] = make_float2(cc.x, a.y);
            *(float2*)&od[4] = make_float2(b.y, cc.y);
        }
        __syncthreads();
    }
}

// ---------------- launch ----------------
extern "C" void kernel_launch(void* const* d_in, const int* in_sizes, int n_in,
                              void* d_out, int out_size) {
    const float* h_i    = (const float*)d_in[0];
    const float* v_i    = (const float*)d_in[1];
    const float* d_ij   = (const float*)d_in[2];
    const float* unit_r = (const float*)d_in[3];
    const void*  nbrs   = (const void*)d_in[4];
    const float* W1     = (const float*)d_in[5];
    const float* b1     = (const float*)d_in[6];
    const float* W2     = (const float*)d_in[7];
    const float* b2     = (const float*)d_in[8];
    const float* Wr     = (const float*)d_in[9];
    const float* br     = (const float*)d_in[10];
    float* out = (float*)d_out;

    int N = in_sizes[0] / FDIM;
    int E = in_sizes[2];

    init_kernel<<<(N + 255) / 256, 256>>>((const int*)nbrs, in_sizes[4], N);
    hist_kernel<<<(E + 255) / 256, 256>>>(nbrs, E);
    scan_kernel<<<1, 1024>>>(N);
    scatter_kernel<<<(E + 255) / 256, 256>>>(nbrs, d_ij, unit_r, E);

    gemm_kernel<<<dim3((N + 63) / 64, 2), 128>>>(h_i, W1, b1, N, FDIM, FDIM, 0);
    gemm_kernel<<<dim3((N + 63) / 64, 6), 128>>>(nullptr, W2, b2, N, PHI_COLS, FDIM, 1);

    node_kernel<<<(N + NPB - 1) / NPB, 128>>>(v_i, Wr, br, out, N);
}

// round 15
// speedup vs baseline: 1.4193x; 1.0838x over previous
#include <cuda_runtime.h>

#define NMAX 20000
#define EMAX 320000
#define FDIM 128
#define PHI_COLS 384
#define NRBF 20
#define NPB 4   // nodes per block in the gather kernel

typedef unsigned long long ull;

// ---------------- scratch (static __device__, no allocations) ----------------
__device__ __align__(16) float g_T[(size_t)NMAX * FDIM];        // silu(h@W1+b1)
__device__ __align__(16) float g_phi[(size_t)NMAX * PHI_COLS];  // phi
__device__ int   g_deg[NMAX];
__device__ int   g_off[NMAX];
__device__ int   g_cur[NMAX];
__device__ int   g_srcs[EMAX];              // sorted-by-dst: src node id
__device__ float g_sd[EMAX];                // sorted-by-dst: d_ij
__device__ __align__(16) float g_su[(size_t)3 * EMAX];          // sorted-by-dst: unit_r
__device__ int   g_is64;   // 1 if nbrs is int64 pairs, 0 if int32 pairs

// ---------------- packed f32x2 helpers (sm_103a) ----------------
__device__ __forceinline__ ull pk2(float x, float y) {
    ull r; asm("mov.b64 %0, {%1, %2};" : "=l"(r) : "f"(x), "f"(y)); return r;
}
__device__ __forceinline__ float2 upk2(ull a) {
    float2 r; asm("mov.b64 {%0, %1}, %2;" : "=f"(r.x), "=f"(r.y) : "l"(a)); return r;
}
__device__ __forceinline__ ull ffma2(ull a, ull b, ull c) {
    ull d; asm("fma.rn.f32x2 %0, %1, %2, %3;" : "=l"(d) : "l"(a), "l"(b), "l"(c)); return d;
}
__device__ __forceinline__ ull fmul2(ull a, ull b) {
    ull d; asm("mul.rn.f32x2 %0, %1, %2;" : "=l"(d) : "l"(a), "l"(b)); return d;
}
__device__ __forceinline__ ull fadd2(ull a, ull b) {
    ull d; asm("add.rn.f32x2 %0, %1, %2;" : "=l"(d) : "l"(a), "l"(b)); return d;
}

__device__ __forceinline__ int2 edge_pair(const void* __restrict__ nbrs, size_t e, int is64) {
    if (is64) {
        const long long* p = (const long long*)nbrs;
        return make_int2((int)p[2 * e], (int)p[2 * e + 1]);
    } else {
        return ((const int2*)nbrs)[e];
    }
}

// ---------------- fused init: zero degrees + nbrs dtype detect ----------------
__global__ void init_kernel(const int* __restrict__ w, int nwords, int Nn) {
    int i = blockIdx.x * 256 + threadIdx.x;
    if (i < Nn) g_deg[i] = 0;
    if (i == 0) {
        int any = 0;
        int lim = nwords < 32 ? nwords : 32;
        for (int k = 1; k < lim; k += 2) any |= w[k];
        g_is64 = (any == 0) ? 1 : 0;
    }
}

__global__ void hist_kernel(const void* __restrict__ nbrs, int E) {
    int is64 = g_is64;
    int e = blockIdx.x * 256 + threadIdx.x;
    if (e < E) {
        int2 p = edge_pair(nbrs, (size_t)e, is64);
        atomicAdd(&g_deg[p.x], 1);
    }
}

// single block, 1024 threads, 20 elems/thread compile-time unrolled, chunked by 20480
__global__ void scan_kernel(int Nn) {
    __shared__ int warpsum[32];
    int t = threadIdx.x, lane = t & 31, w = t >> 5;
    int run = 0;
    for (int base = 0; base < Nn; base += 20480) {
        int vals[20];
        int s = 0;
        int i0 = base + t * 20;
#pragma unroll
        for (int k = 0; k < 20; ++k) {
            int i = i0 + k;
            int v = (i < Nn) ? g_deg[i] : 0;
            vals[k] = s;
            s += v;
        }
        int x = s;
#pragma unroll
        for (int off = 1; off < 32; off <<= 1) {
            int y = __shfl_up_sync(0xFFFFFFFFu, x, off);
            if (lane >= off) x += y;
        }
        if (lane == 31) warpsum[w] = x;
        __syncthreads();
        if (w == 0) {
            int y = warpsum[lane];
#pragma unroll
            for (int off = 1; off < 32; off <<= 1) {
                int z = __shfl_up_sync(0xFFFFFFFFu, y, off);
                if (lane >= off) y += z;
            }
            warpsum[lane] = y;
        }
        __syncthreads();
        int excl = run + x - s + ((w > 0) ? warpsum[w - 1] : 0);
#pragma unroll
        for (int k = 0; k < 20; ++k) {
            int i = i0 + k;
            if (i < Nn) { g_off[i] = excl + vals[k]; g_cur[i] = excl + vals[k]; }
        }
        run += warpsum[31];
        __syncthreads();
    }
}

// scatter edges into dst-sorted arrays (src, d, unit_r)
__global__ void scatter_kernel(const void* __restrict__ nbrs,
                               const float* __restrict__ d_ij,
                               const float* __restrict__ ur, int E) {
    int is64 = g_is64;
    int e = blockIdx.x * 256 + threadIdx.x;
    if (e < E) {
        int2 p = edge_pair(nbrs, (size_t)e, is64);
        int pos = atomicAdd(&g_cur[p.x], 1);
        g_srcs[pos] = p.y;
        g_sd[pos] = d_ij[e];
        g_su[3 * (size_t)pos + 0] = ur[3 * (size_t)e + 0];
        g_su[3 * (size_t)pos + 1] = ur[3 * (size_t)e + 1];
        g_su[3 * (size_t)pos + 2] = ur[3 * (size_t)e + 2];
    }
}

// ---------------- tiled fp32 GEMM with packed f32x2 micro-kernel ----------------
__global__ __launch_bounds__(128) void gemm_kernel(
    const float* __restrict__ Aext, const float* __restrict__ B,
    const float* __restrict__ bias, int M, int Ncols, int K, int mode)
{
    const float* __restrict__ A = (mode == 0) ? Aext : (const float*)g_T;
    float* C = (mode == 0) ? g_T : g_phi;

    __shared__ __align__(16) float As[16][64];
    __shared__ __align__(16) float Bs[16][64];

    int tid = threadIdx.x;
    int m0 = blockIdx.x * 64;
    int n0 = blockIdx.y * 64;
    int tr = tid >> 4;
    int tc = tid & 15;

    ull acc2[4][4];
#pragma unroll
    for (int i = 0; i < 4; ++i)
#pragma unroll
        for (int j = 0; j < 4; ++j) acc2[i][j] = 0ull;

    for (int kt = 0; kt < K; kt += 16) {
#pragma unroll
        for (int l = 0; l < 2; ++l) {
            int q = tid + l * 128;
            int row = q >> 2;
            int kc = (q & 3) * 4;
            float4 av = make_float4(0.f, 0.f, 0.f, 0.f);
            int gm = m0 + row;
            if (gm < M) av = *(const float4*)&A[(size_t)gm * K + kt + kc];
            As[kc + 0][row] = av.x; As[kc + 1][row] = av.y;
            As[kc + 2][row] = av.z; As[kc + 3][row] = av.w;
        }
#pragma unroll
        for (int l = 0; l < 2; ++l) {
            int q = tid + l * 128;
            int row = q >> 4;
            int cc = (q & 15) * 4;
            *(float4*)&Bs[row][cc] = *(const float4*)&B[(size_t)(kt + row) * Ncols + n0 + cc];
        }
        __syncthreads();
#pragma unroll
        for (int k = 0; k < 16; ++k) {
            ull aa[4];
#pragma unroll
            for (int i = 0; i < 4; ++i)
                aa[i] = *(const ull*)&As[k][tr * 8 + i * 2];
            float b[4];
            *(float4*)&b[0] = *(const float4*)&Bs[k][tc * 4];
#pragma unroll
            for (int j = 0; j < 4; ++j) {
                ull bv = pk2(b[j], b[j]);
#pragma unroll
                for (int i = 0; i < 4; ++i)
                    acc2[i][j] = ffma2(aa[i], bv, acc2[i][j]);
            }
        }
        __syncthreads();
    }

    float bv[4];
    *(float4*)bv = *(const float4*)&bias[n0 + tc * 4];
#pragma unroll
    for (int i2 = 0; i2 < 4; ++i2) {
        float2 c0 = upk2(acc2[i2][0]), c1 = upk2(acc2[i2][1]);
        float2 c2 = upk2(acc2[i2][2]), c3 = upk2(acc2[i2][3]);
        float4 row0 = make_float4(c0.x + bv[0], c1.x + bv[1], c2.x + bv[2], c3.x + bv[3]);
        float4 row1 = make_float4(c0.y + bv[0], c1.y + bv[1], c2.y + bv[2], c3.y + bv[3]);
        if (mode == 0) {
            row0.x = row0.x / (1.0f + __expf(-row0.x));
            row0.y = row0.y / (1.0f + __expf(-row0.y));
            row0.z = row0.z / (1.0f + __expf(-row0.z));
            row0.w = row0.w / (1.0f + __expf(-row0.w));
            row1.x = row1.x / (1.0f + __expf(-row1.x));
            row1.y = row1.y / (1.0f + __expf(-row1.y));
            row1.z = row1.z / (1.0f + __expf(-row1.z));
            row1.w = row1.w / (1.0f + __expf(-row1.w));
        }
        int gm0 = m0 + tr * 8 + i2 * 2;
        if (gm0 < M)     *(float4*)&C[(size_t)gm0 * Ncols + n0 + tc * 4] = row0;
        if (gm0 + 1 < M) *(float4*)&C[(size_t)(gm0 + 1) * Ncols + n0 + tc * 4] = row1;
    }
}

// ---------------- per-edge state for the dual-edge pipeline ----------------
struct EdgeStage {
    ull p0, p1, p2, v0, v1, v2;
    float d, u0, u1, u2;
    float fc;   // validity-folded: 0 if lane invalid (handled via fcut)
};

__device__ __forceinline__ void load_edge(EdgeStage& st, int pos, int valid,
                                          const float* __restrict__ v_i, int f0) {
    st.fc = valid ? 1.0f : 0.0f;   // multiplied into fcut later
    int src = g_srcs[pos];
    st.d = g_sd[pos];
    st.u0 = g_su[3 * (size_t)pos + 0];
    st.u1 = g_su[3 * (size_t)pos + 1];
    st.u2 = g_su[3 * (size_t)pos + 2];
    const float* pb = &g_phi[(size_t)src * PHI_COLS + f0];
    st.p0 = *(const ull*)(pb);
    st.p1 = *(const ull*)(pb + FDIM);
    st.p2 = *(const ull*)(pb + 2 * FDIM);
    const float* vb = &v_i[(size_t)src * (FDIM * 3) + (size_t)f0 * 3];
    st.v0 = pk2(vb[0], vb[3]);
    st.v1 = pk2(vb[1], vb[4]);
    st.v2 = pk2(vb[2], vb[5]);
}

// ---------------- gather node kernel: 2 slots x 64 threads, 2 edges/thread/iter ----------------
__global__ __launch_bounds__(128) void node_kernel(
    const float* __restrict__ v_i,
    const float* __restrict__ Wr, const float* __restrict__ br,
    float* __restrict__ out, int Nn)
{
    int tid = threadIdx.x;
    int sub = tid >> 6;       // edge-slot 0/1
    int t = tid & 63;
    int f0 = t * 2;           // features f0, f0+1

    ull W0[NRBF], W1r[NRBF], W2r[NRBF];
#pragma unroll
    for (int r = 0; r < NRBF; ++r) {
        W0[r]  = *(const ull*)&Wr[(size_t)r * PHI_COLS + 0 * FDIM + f0];
        W1r[r] = *(const ull*)&Wr[(size_t)r * PHI_COLS + 1 * FDIM + f0];
        W2r[r] = *(const ull*)&Wr[(size_t)r * PHI_COLS + 2 * FDIM + f0];
    }
    ull B0 = *(const ull*)&br[0 * FDIM + f0];
    ull B1 = *(const ull*)&br[1 * FDIM + f0];
    ull B2 = *(const ull*)&br[2 * FDIM + f0];

    __shared__ float sh[64 * 8];

    for (int nn = 0; nn < NPB; ++nn) {
        int n = blockIdx.x * NPB + nn;
        if (n >= Nn) break;

        int beg = g_off[n];
        int deg = g_deg[n];

        ull dh = 0ull, dva = 0ull, dvb = 0ull, dvc = 0ull;

        // slot s handles pairs {4k+2s, 4k+2s+1}
        EdgeStage cA, cB;
        int base0 = sub * 2;
        if (base0 < deg) {
            int ja = base0, jb = base0 + 1;
            int pa = beg + ja;
            int pb_ = beg + ((jb < deg) ? jb : ja);
            load_edge(cA, pa, 1, v_i, f0);
            load_edge(cB, pb_, (jb < deg) ? 1 : 0, v_i, f0);
        }

        for (int j = base0; j < deg; j += 4) {
            EdgeStage a = cA, b = cB;

            int jn = j + 4;
            if (jn < deg) {
                int pa = beg + jn;
                int jb = jn + 1;
                int pb_ = beg + ((jb < deg) ? jb : jn);
                load_edge(cA, pa, 1, v_i, f0);
                load_edge(cB, pb_, (jb < deg) ? 1 : 0, v_i, f0);
            }

            // ---- edge A scalars ----
            float xA = a.d * 0.62831853071795864769f;
            float sA, cAx;
            __sincosf(xA, &sA, &cAx);
            float fcsA = ((a.d < 5.0f) ? 0.5f * (cAx + 1.0f) : 0.0f) * a.fc;
            float invdA = __frcp_rn(a.d);
            float twocA = cAx + cAx;
            // ---- edge B scalars ----
            float xB = b.d * 0.62831853071795864769f;
            float sB, cBx;
            __sincosf(xB, &sB, &cBx);
            float fcsB = ((b.d < 5.0f) ? 0.5f * (cBx + 1.0f) : 0.0f) * b.fc;
            float invdB = __frcp_rn(b.d);
            float twocB = cBx + cBx;

            // ---- interleaved Chebyshev matvecs (independent chains) ----
            ull a0 = 0ull, a1 = 0ull, a2 = 0ull;
            ull b0 = 0ull, b1 = 0ull, b2 = 0ull;
            float spA = 0.0f, snA = sA;
            float spB = 0.0f, snB = sB;
#pragma unroll
            for (int r = 0; r < NRBF; ++r) {
                ull svA = pk2(snA, snA);
                ull svB = pk2(snB, snB);
                a0 = ffma2(svA, W0[r], a0);
                b0 = ffma2(svB, W0[r], b0);
                a1 = ffma2(svA, W1r[r], a1);
                b1 = ffma2(svB, W1r[r], b1);
                a2 = ffma2(svA, W2r[r], a2);
                b2 = ffma2(svB, W2r[r], b2);
                float s2A = __fmaf_rn(twocA, snA, -spA);
                float s2B = __fmaf_rn(twocB, snB, -spB);
                spA = snA; snA = s2A;
                spB = snB; snB = s2B;
            }

            // ---- epilogues ----
            {
                ull invdv = pk2(invdA, invdA);
                ull fcv = pk2(fcsA, fcsA);
                ull e0 = fmul2(ffma2(a0, invdv, B0), fcv);
                ull e1 = fmul2(ffma2(a1, invdv, B1), fcv);
                ull e2 = fmul2(ffma2(a2, invdv, B2), fcv);
                ull gm0 = fmul2(a.p0, e0);
                ull gm1 = fmul2(a.p1, e1);
                ull gm2 = fmul2(a.p2, e2);
                dh = fadd2(dh, gm2);
                dva = ffma2(gm0, pk2(a.u0, a.u0), ffma2(gm1, a.v0, dva));
                dvb = ffma2(gm0, pk2(a.u1, a.u1), ffma2(gm1, a.v1, dvb));
                dvc = ffma2(gm0, pk2(a.u2, a.u2), ffma2(gm1, a.v2, dvc));
            }
            {
                ull invdv = pk2(invdB, invdB);
                ull fcv = pk2(fcsB, fcsB);
                ull e0 = fmul2(ffma2(b0, invdv, B0), fcv);
                ull e1 = fmul2(ffma2(b1, invdv, B1), fcv);
                ull e2 = fmul2(ffma2(b2, invdv, B2), fcv);
                ull gm0 = fmul2(b.p0, e0);
                ull gm1 = fmul2(b.p1, e1);
                ull gm2 = fmul2(b.p2, e2);
                dh = fadd2(dh, gm2);
                dva = ffma2(gm0, pk2(b.u0, b.u0), ffma2(gm1, b.v0, dva));
                dvb = ffma2(gm0, pk2(b.u1, b.u1), ffma2(gm1, b.v1, dvb));
                dvc = ffma2(gm0, pk2(b.u2, b.u2), ffma2(gm1, b.v2, dvc));
            }
        }

        if (sub == 1) {
            float2 h = upk2(dh), a = upk2(dva), b = upk2(dvb), cc = upk2(dvc);
            float* p = &sh[t * 8];
            p[0] = h.x; p[1] = h.y; p[2] = a.x; p[3] = a.y;
            p[4] = b.x; p[5] = b.y; p[6] = cc.x; p[7] = cc.y;
        }
        __syncthreads();
        if (sub == 0) {
            float2 h = upk2(dh), a = upk2(dva), b = upk2(dvb), cc = upk2(dvc);
            const float* p = &sh[t * 8];
            h.x += p[0]; h.y += p[1]; a.x += p[2]; a.y += p[3];
            b.x += p[4]; b.y += p[5]; cc.x += p[6]; cc.y += p[7];

            *(float2*)&out[(size_t)n * FDIM + f0] = make_float2(h.x, h.y);
            float* od = out + (size_t)Nn * FDIM + (size_t)n * (FDIM * 3) + (size_t)f0 * 3;
            *(float2*)&od[0] = make_float2(a.x, b.x);
            *(float2*)&od[2] = make_float2(cc.x, a.y);
            *(float2*)&od[4] = make_float2(b.y, cc.y);
        }
        __syncthreads();
    }
}

// ---------------- launch ----------------
// Order chosen so the 4th launch (ncu capture window) is the big GEMM (gemm1).
extern "C" void kernel_launch(void* const* d_in, const int* in_sizes, int n_in,
                              void* d_out, int out_size) {
    const float* h_i    = (const float*)d_in[0];
    const float* v_i    = (const float*)d_in[1];
    const float* d_ij   = (const float*)d_in[2];
    const float* unit_r = (const float*)d_in[3];
    const void*  nbrs   = (const void*)d_in[4];
    const float* W1     = (const float*)d_in[5];
    const float* b1     = (const float*)d_in[6];
    const float* W2     = (const float*)d_in[7];
    const float* b2     = (const float*)d_in[8];
    const float* Wr     = (const float*)d_in[9];
    const float* br     = (const float*)d_in[10];
    float* out = (float*)d_out;

    int N = in_sizes[0] / FDIM;
    int E = in_sizes[2];

    init_kernel<<<(N + 255) / 256, 256>>>((const int*)nbrs, in_sizes[4], N);
    hist_kernel<<<(E + 255) / 256, 256>>>(nbrs, E);
    gemm_kernel<<<dim3((N + 63) / 64, 2), 128>>>(h_i, W1, b1, N, FDIM, FDIM, 0);
    gemm_kernel<<<dim3((N + 63) / 64, 6), 128>>>(nullptr, W2, b2, N, PHI_COLS, FDIM, 1);
    scan_kernel<<<1, 1024>>>(N);
    scatter_kernel<<<(E + 255) / 256, 256>>>(nbrs, d_ij, unit_r, E);

    node_kernel<<<(N + NPB - 1) / NPB, 128>>>(v_i, Wr, br, out, N);
}

// round 16
// speedup vs baseline: 1.4723x; 1.0374x over previous
#include <cuda_runtime.h>

#define NMAX 20000
#define EMAX 320000
#define FDIM 128
#define PHI_COLS 384
#define NRBF 20
#define NPB 4   // nodes per block in the gather kernel

typedef unsigned long long ull;

// ---------------- scratch (static __device__, no allocations) ----------------
__device__ __align__(16) float g_T[(size_t)NMAX * FDIM];        // silu(h@W1+b1)
__device__ __align__(16) float g_phi[(size_t)NMAX * PHI_COLS];  // phi
__device__ int   g_deg[NMAX];
__device__ int   g_off[NMAX];
__device__ int   g_cur[NMAX];
__device__ int   g_srcs[EMAX];              // sorted-by-dst: src node id
__device__ float g_sd[EMAX];                // sorted-by-dst: d_ij
__device__ __align__(16) float g_su[(size_t)3 * EMAX];          // sorted-by-dst: unit_r
__device__ int   g_is64;   // 1 if nbrs is int64 pairs, 0 if int32 pairs

// ---------------- packed f32x2 helpers (sm_103a) ----------------
__device__ __forceinline__ ull pk2(float x, float y) {
    ull r; asm("mov.b64 %0, {%1, %2};" : "=l"(r) : "f"(x), "f"(y)); return r;
}
__device__ __forceinline__ float2 upk2(ull a) {
    float2 r; asm("mov.b64 {%0, %1}, %2;" : "=f"(r.x), "=f"(r.y) : "l"(a)); return r;
}
__device__ __forceinline__ ull ffma2(ull a, ull b, ull c) {
    ull d; asm("fma.rn.f32x2 %0, %1, %2, %3;" : "=l"(d) : "l"(a), "l"(b), "l"(c)); return d;
}
__device__ __forceinline__ ull fmul2(ull a, ull b) {
    ull d; asm("mul.rn.f32x2 %0, %1, %2;" : "=l"(d) : "l"(a), "l"(b)); return d;
}
__device__ __forceinline__ ull fadd2(ull a, ull b) {
    ull d; asm("add.rn.f32x2 %0, %1, %2;" : "=l"(d) : "l"(a), "l"(b)); return d;
}

__device__ __forceinline__ int2 edge_pair(const void* __restrict__ nbrs, size_t e, int is64) {
    if (is64) {
        const long long* p = (const long long*)nbrs;
        return make_int2((int)p[2 * e], (int)p[2 * e + 1]);
    } else {
        return ((const int2*)nbrs)[e];
    }
}

// ---------------- fused init: zero degrees + nbrs dtype detect ----------------
__global__ void init_kernel(const int* __restrict__ w, int nwords, int Nn) {
    int i = blockIdx.x * 256 + threadIdx.x;
    if (i < Nn) g_deg[i] = 0;
    if (i == 0) {
        int any = 0;
        int lim = nwords < 32 ? nwords : 32;
        for (int k = 1; k < lim; k += 2) any |= w[k];
        g_is64 = (any == 0) ? 1 : 0;
    }
}

__global__ void hist_kernel(const void* __restrict__ nbrs, int E) {
    int is64 = g_is64;
    int e = blockIdx.x * 256 + threadIdx.x;
    if (e < E) {
        int2 p = edge_pair(nbrs, (size_t)e, is64);
        atomicAdd(&g_deg[p.x], 1);
    }
}

// single block, 1024 threads, 20 elems/thread compile-time unrolled, chunked by 20480
__global__ void scan_kernel(int Nn) {
    __shared__ int warpsum[32];
    int t = threadIdx.x, lane = t & 31, w = t >> 5;
    int run = 0;
    for (int base = 0; base < Nn; base += 20480) {
        int vals[20];
        int s = 0;
        int i0 = base + t * 20;
#pragma unroll
        for (int k = 0; k < 20; ++k) {
            int i = i0 + k;
            int v = (i < Nn) ? g_deg[i] : 0;
            vals[k] = s;
            s += v;
        }
        int x = s;
#pragma unroll
        for (int off = 1; off < 32; off <<= 1) {
            int y = __shfl_up_sync(0xFFFFFFFFu, x, off);
            if (lane >= off) x += y;
        }
        if (lane == 31) warpsum[w] = x;
        __syncthreads();
        if (w == 0) {
            int y = warpsum[lane];
#pragma unroll
            for (int off = 1; off < 32; off <<= 1) {
                int z = __shfl_up_sync(0xFFFFFFFFu, y, off);
                if (lane >= off) y += z;
            }
            warpsum[lane] = y;
        }
        __syncthreads();
        int excl = run + x - s + ((w > 0) ? warpsum[w - 1] : 0);
#pragma unroll
        for (int k = 0; k < 20; ++k) {
            int i = i0 + k;
            if (i < Nn) { g_off[i] = excl + vals[k]; g_cur[i] = excl + vals[k]; }
        }
        run += warpsum[31];
        __syncthreads();
    }
}

// scatter edges into dst-sorted arrays (src, d, unit_r)
__global__ void scatter_kernel(const void* __restrict__ nbrs,
                               const float* __restrict__ d_ij,
                               const float* __restrict__ ur, int E) {
    int is64 = g_is64;
    int e = blockIdx.x * 256 + threadIdx.x;
    if (e < E) {
        int2 p = edge_pair(nbrs, (size_t)e, is64);
        int pos = atomicAdd(&g_cur[p.x], 1);
        g_srcs[pos] = p.y;
        g_sd[pos] = d_ij[e];
        g_su[3 * (size_t)pos + 0] = ur[3 * (size_t)e + 0];
        g_su[3 * (size_t)pos + 1] = ur[3 * (size_t)e + 1];
        g_su[3 * (size_t)pos + 2] = ur[3 * (size_t)e + 2];
    }
}

// ---------------- tiled fp32 GEMM with packed f32x2 micro-kernel ----------------
__global__ __launch_bounds__(128) void gemm_kernel(
    const float* __restrict__ Aext, const float* __restrict__ B,
    const float* __restrict__ bias, int M, int Ncols, int K, int mode)
{
    const float* __restrict__ A = (mode == 0) ? Aext : (const float*)g_T;
    float* C = (mode == 0) ? g_T : g_phi;

    __shared__ __align__(16) float As[16][64];
    __shared__ __align__(16) float Bs[16][64];

    int tid = threadIdx.x;
    int m0 = blockIdx.x * 64;
    int n0 = blockIdx.y * 64;
    int tr = tid >> 4;
    int tc = tid & 15;

    ull acc2[4][4];
#pragma unroll
    for (int i = 0; i < 4; ++i)
#pragma unroll
        for (int j = 0; j < 4; ++j) acc2[i][j] = 0ull;

    for (int kt = 0; kt < K; kt += 16) {
#pragma unroll
        for (int l = 0; l < 2; ++l) {
            int q = tid + l * 128;
            int row = q >> 2;
            int kc = (q & 3) * 4;
            float4 av = make_float4(0.f, 0.f, 0.f, 0.f);
            int gm = m0 + row;
            if (gm < M) av = *(const float4*)&A[(size_t)gm * K + kt + kc];
            As[kc + 0][row] = av.x; As[kc + 1][row] = av.y;
            As[kc + 2][row] = av.z; As[kc + 3][row] = av.w;
        }
#pragma unroll
        for (int l = 0; l < 2; ++l) {
            int q = tid + l * 128;
            int row = q >> 4;
            int cc = (q & 15) * 4;
            *(float4*)&Bs[row][cc] = *(const float4*)&B[(size_t)(kt + row) * Ncols + n0 + cc];
        }
        __syncthreads();
#pragma unroll
        for (int k = 0; k < 16; ++k) {
            ull aa[4];
#pragma unroll
            for (int i = 0; i < 4; ++i)
                aa[i] = *(const ull*)&As[k][tr * 8 + i * 2];
            float b[4];
            *(float4*)&b[0] = *(const float4*)&Bs[k][tc * 4];
#pragma unroll
            for (int j = 0; j < 4; ++j) {
                ull bv = pk2(b[j], b[j]);
#pragma unroll
                for (int i = 0; i < 4; ++i)
                    acc2[i][j] = ffma2(aa[i], bv, acc2[i][j]);
            }
        }
        __syncthreads();
    }

    float bv[4];
    *(float4*)bv = *(const float4*)&bias[n0 + tc * 4];
#pragma unroll
    for (int i2 = 0; i2 < 4; ++i2) {
        float2 c0 = upk2(acc2[i2][0]), c1 = upk2(acc2[i2][1]);
        float2 c2 = upk2(acc2[i2][2]), c3 = upk2(acc2[i2][3]);
        float4 row0 = make_float4(c0.x + bv[0], c1.x + bv[1], c2.x + bv[2], c3.x + bv[3]);
        float4 row1 = make_float4(c0.y + bv[0], c1.y + bv[1], c2.y + bv[2], c3.y + bv[3]);
        if (mode == 0) {
            row0.x = row0.x / (1.0f + __expf(-row0.x));
            row0.y = row0.y / (1.0f + __expf(-row0.y));
            row0.z = row0.z / (1.0f + __expf(-row0.z));
            row0.w = row0.w / (1.0f + __expf(-row0.w));
            row1.x = row1.x / (1.0f + __expf(-row1.x));
            row1.y = row1.y / (1.0f + __expf(-row1.y));
            row1.z = row1.z / (1.0f + __expf(-row1.z));
            row1.w = row1.w / (1.0f + __expf(-row1.w));
        }
        int gm0 = m0 + tr * 8 + i2 * 2;
        if (gm0 < M)     *(float4*)&C[(size_t)gm0 * Ncols + n0 + tc * 4] = row0;
        if (gm0 + 1 < M) *(float4*)&C[(size_t)(gm0 + 1) * Ncols + n0 + tc * 4] = row1;
    }
}

// ---------------- per-edge state for the dual-edge pipeline ----------------
struct EdgeStage {
    ull p0, p1, p2, v0, v1, v2;
    float d, u0, u1, u2;
    float fc;   // validity-folded: 0 if lane invalid (handled via fcut)
};

__device__ __forceinline__ void load_edge(EdgeStage& st, int pos, int valid,
                                          const float* __restrict__ v_i, int f0) {
    st.fc = valid ? 1.0f : 0.0f;   // multiplied into fcut later
    int src = g_srcs[pos];
    st.d = g_sd[pos];
    st.u0 = g_su[3 * (size_t)pos + 0];
    st.u1 = g_su[3 * (size_t)pos + 1];
    st.u2 = g_su[3 * (size_t)pos + 2];
    const float* pb = &g_phi[(size_t)src * PHI_COLS + f0];
    st.p0 = *(const ull*)(pb);
    st.p1 = *(const ull*)(pb + FDIM);
    st.p2 = *(const ull*)(pb + 2 * FDIM);
    // v_i for features f0, f0+1: 24 contiguous bytes, 8B-aligned -> 3x LDG.64
    const float2* vb2 = (const float2*)&v_i[(size_t)src * (FDIM * 3) + (size_t)f0 * 3];
    float2 q0 = vb2[0], q1 = vb2[1], q2 = vb2[2];
    st.v0 = pk2(q0.x, q1.y);   // (f0.x, f1.x)
    st.v1 = pk2(q0.y, q2.x);   // (f0.y, f1.y)
    st.v2 = pk2(q1.x, q2.y);   // (f0.z, f1.z)
}

// ---------------- gather node kernel: 2 slots x 64 threads, 2 edges/thread/iter,
// cross-node prologue prefetch, streaming output stores ----------------
__global__ __launch_bounds__(128) void node_kernel(
    const float* __restrict__ v_i,
    const float* __restrict__ Wr, const float* __restrict__ br,
    float* __restrict__ out, int Nn)
{
    int tid = threadIdx.x;
    int sub = tid >> 6;       // edge-slot 0/1
    int t = tid & 63;
    int f0 = t * 2;           // features f0, f0+1

    ull W0[NRBF], W1r[NRBF], W2r[NRBF];
#pragma unroll
    for (int r = 0; r < NRBF; ++r) {
        W0[r]  = *(const ull*)&Wr[(size_t)r * PHI_COLS + 0 * FDIM + f0];
        W1r[r] = *(const ull*)&Wr[(size_t)r * PHI_COLS + 1 * FDIM + f0];
        W2r[r] = *(const ull*)&Wr[(size_t)r * PHI_COLS + 2 * FDIM + f0];
    }
    ull B0 = *(const ull*)&br[0 * FDIM + f0];
    ull B1 = *(const ull*)&br[1 * FDIM + f0];
    ull B2 = *(const ull*)&br[2 * FDIM + f0];

    __shared__ float sh[64 * 8];

    int n0blk = blockIdx.x * NPB;

    // prologue for first node
    int beg = 0, deg = 0;
    EdgeStage cA, cB;
    if (n0blk < Nn) {
        beg = g_off[n0blk];
        deg = g_deg[n0blk];
        int base0 = sub * 2;
        if (base0 < deg) {
            int ja = base0, jb = base0 + 1;
            load_edge(cA, beg + ja, 1, v_i, f0);
            load_edge(cB, beg + ((jb < deg) ? jb : ja), (jb < deg) ? 1 : 0, v_i, f0);
        }
    }

    for (int nn = 0; nn < NPB; ++nn) {
        int n = n0blk + nn;
        if (n >= Nn) break;

        ull dh = 0ull, dva = 0ull, dvb = 0ull, dvc = 0ull;

        int base0 = sub * 2;
        for (int j = base0; j < deg; j += 4) {
            EdgeStage a = cA, b = cB;

            int jn = j + 4;
            if (jn < deg) {
                int jb = jn + 1;
                load_edge(cA, beg + jn, 1, v_i, f0);
                load_edge(cB, beg + ((jb < deg) ? jb : jn), (jb < deg) ? 1 : 0, v_i, f0);
            }

            // ---- edge A scalars ----
            float xA = a.d * 0.62831853071795864769f;
            float sA, cAx;
            __sincosf(xA, &sA, &cAx);
            float fcsA = ((a.d < 5.0f) ? 0.5f * (cAx + 1.0f) : 0.0f) * a.fc;
            float invdA = __frcp_rn(a.d);
            float twocA = cAx + cAx;
            // ---- edge B scalars ----
            float xB = b.d * 0.62831853071795864769f;
            float sB, cBx;
            __sincosf(xB, &sB, &cBx);
            float fcsB = ((b.d < 5.0f) ? 0.5f * (cBx + 1.0f) : 0.0f) * b.fc;
            float invdB = __frcp_rn(b.d);
            float twocB = cBx + cBx;

            // ---- interleaved Chebyshev matvecs (independent chains) ----
            ull a0 = 0ull, a1 = 0ull, a2 = 0ull;
            ull b0 = 0ull, b1 = 0ull, b2 = 0ull;
            float spA = 0.0f, snA = sA;
            float spB = 0.0f, snB = sB;
#pragma unroll
            for (int r = 0; r < NRBF; ++r) {
                ull svA = pk2(snA, snA);
                ull svB = pk2(snB, snB);
                a0 = ffma2(svA, W0[r], a0);
                b0 = ffma2(svB, W0[r], b0);
                a1 = ffma2(svA, W1r[r], a1);
                b1 = ffma2(svB, W1r[r], b1);
                a2 = ffma2(svA, W2r[r], a2);
                b2 = ffma2(svB, W2r[r], b2);
                float s2A = __fmaf_rn(twocA, snA, -spA);
                float s2B = __fmaf_rn(twocB, snB, -spB);
                spA = snA; snA = s2A;
                spB = snB; snB = s2B;
            }

            // ---- epilogues ----
            {
                ull invdv = pk2(invdA, invdA);
                ull fcv = pk2(fcsA, fcsA);
                ull e0 = fmul2(ffma2(a0, invdv, B0), fcv);
                ull e1 = fmul2(ffma2(a1, invdv, B1), fcv);
                ull e2 = fmul2(ffma2(a2, invdv, B2), fcv);
                ull gm0 = fmul2(a.p0, e0);
                ull gm1 = fmul2(a.p1, e1);
                ull gm2 = fmul2(a.p2, e2);
                dh = fadd2(dh, gm2);
                dva = ffma2(gm0, pk2(a.u0, a.u0), ffma2(gm1, a.v0, dva));
                dvb = ffma2(gm0, pk2(a.u1, a.u1), ffma2(gm1, a.v1, dvb));
                dvc = ffma2(gm0, pk2(a.u2, a.u2), ffma2(gm1, a.v2, dvc));
            }
            {
                ull invdv = pk2(invdB, invdB);
                ull fcv = pk2(fcsB, fcsB);
                ull e0 = fmul2(ffma2(b0, invdv, B0), fcv);
                ull e1 = fmul2(ffma2(b1, invdv, B1), fcv);
                ull e2 = fmul2(ffma2(b2, invdv, B2), fcv);
                ull gm0 = fmul2(b.p0, e0);
                ull gm1 = fmul2(b.p1, e1);
                ull gm2 = fmul2(b.p2, e2);
                dh = fadd2(dh, gm2);
                dva = ffma2(gm0, pk2(b.u0, b.u0), ffma2(gm1, b.v0, dva));
                dvb = ffma2(gm0, pk2(b.u1, b.u1), ffma2(gm1, b.v1, dvb));
                dvc = ffma2(gm0, pk2(b.u2, b.u2), ffma2(gm1, b.v2, dvc));
            }
        }

        // ---- cross-node prefetch: issue next node's prologue gathers BEFORE
        // the combine/sync/write phase so their latency overlaps it ----
        int n2 = n + 1;
        int beg2 = 0, deg2 = 0;
        if (nn + 1 < NPB && n2 < Nn) {
            beg2 = g_off[n2];
            deg2 = g_deg[n2];
            int b0n = sub * 2;
            if (b0n < deg2) {
                int ja = b0n, jb = b0n + 1;
                load_edge(cA, beg2 + ja, 1, v_i, f0);
                load_edge(cB, beg2 + ((jb < deg2) ? jb : ja), (jb < deg2) ? 1 : 0, v_i, f0);
            }
        }

        // combine the two edge-slot partials, slot 0 writes output (streaming)
        if (sub == 1) {
            float2 h = upk2(dh), a = upk2(dva), b = upk2(dvb), cc = upk2(dvc);
            float* p = &sh[t * 8];
            p[0] = h.x; p[1] = h.y; p[2] = a.x; p[3] = a.y;
            p[4] = b.x; p[5] = b.y; p[6] = cc.x; p[7] = cc.y;
        }
        __syncthreads();
        if (sub == 0) {
            float2 h = upk2(dh), a = upk2(dva), b = upk2(dvb), cc = upk2(dvc);
            const float* p = &sh[t * 8];
            h.x += p[0]; h.y += p[1]; a.x += p[2]; a.y += p[3];
            b.x += p[4]; b.y += p[5]; cc.x += p[6]; cc.y += p[7];

            __stcs((float2*)&out[(size_t)n * FDIM + f0], make_float2(h.x, h.y));
            float* od = out + (size_t)Nn * FDIM + (size_t)n * (FDIM * 3) + (size_t)f0 * 3;
            __stcs((float2*)&od[0], make_float2(a.x, b.x));
            __stcs((float2*)&od[2], make_float2(cc.x, a.y));
            __stcs((float2*)&od[4], make_float2(b.y, cc.y));
        }
        __syncthreads();

        beg = beg2; deg = deg2;
    }
}

// ---------------- launch ----------------
// Order keeps gemm1 as the 4th launch (the ncu capture window).
extern "C" void kernel_launch(void* const* d_in, const int* in_sizes, int n_in,
                              void* d_out, int out_size) {
    const float* h_i    = (const float*)d_in[0];
    const float* v_i    = (const float*)d_in[1];
    const float* d_ij   = (const float*)d_in[2];
    const float* unit_r = (const float*)d_in[3];
    const void*  nbrs   = (const void*)d_in[4];
    const float* W1     = (const float*)d_in[5];
    const float* b1     = (const float*)d_in[6];
    const float* W2     = (const float*)d_in[7];
    const float* b2     = (const float*)d_in[8];
    const float* Wr     = (const float*)d_in[9];
    const float* br     = (const float*)d_in[10];
    float* out = (float*)d_out;

    int N = in_sizes[0] / FDIM;
    int E = in_sizes[2];

    init_kernel<<<(N + 255) / 256, 256>>>((const int*)nbrs, in_sizes[4], N);
    hist_kernel<<<(E + 255) / 256, 256>>>(nbrs, E);
    gemm_kernel<<<dim3((N + 63) / 64, 2), 128>>>(h_i, W1, b1, N, FDIM, FDIM, 0);
    gemm_kernel<<<dim3((N + 63) / 64, 6), 128>>>(nullptr, W2, b2, N, PHI_COLS, FDIM, 1);
    scan_kernel<<<1, 1024>>>(N);
    scatter_kernel<<<(E + 255) / 256, 256>>>(nbrs, d_ij, unit_r, E);

    node_kernel<<<(N + NPB - 1) / NPB, 128>>>(v_i, Wr, br, out, N);
}